// round 15
// baseline (speedup 1.0000x reference)
#include <cuda_runtime.h>
#include <cuda_fp16.h>
#include <mma.h>
#include <math.h>

using namespace nvcuda;

#define N_NODES 50000
#define N_EDGES 1600000
#define D_IN    256
#define D_OUT   64
#define D_HID   128   // 2*D_OUT, concat layout: [high(0..63) | low(64..127)]

#define ALPHA    0.2f
#define BT_SLOPE 0.01f

#define NB_SCAN 49    // ceil(50000/1024)

// ---------------- scratch (device globals; no cudaMalloc allowed) ----------------
__device__ float g_Wc[D_IN * D_HID];              // combined [256][128] weight, tf32-rounded
__device__ uint4 g_Hh4[N_NODES * 16];             // fp16 activated H: 128 halves/node = 16 uint4
__device__ float2 g_s2[N_NODES];                  // (s_high, s_low) per node
__device__ int g_hist[N_NODES];
__device__ int g_scan_local[N_NODES];             // inclusive scan within 1024-tile
__device__ int g_blocksum[64];
__device__ int g_blockpref[64];                   // exclusive scan of block sums
__device__ int g_cursor[N_NODES];
__device__ int g_csr_dst[N_EDGES];
__device__ int g_edge_is64;
__device__ int g_scan_ticket;

__device__ __forceinline__ void cp_async16(void* sptr, const void* gptr) {
    unsigned saddr = (unsigned)__cvta_generic_to_shared(sptr);
    asm volatile("cp.async.cg.shared.global [%0], [%1], 16;" :: "r"(saddr), "l"(gptr));
}

// exclusive prefix of hist at i (i in [0, N_NODES])
__device__ __forceinline__ int row_start_at(int i) {
    if (i == 0) return 0;
    int j = i - 1;
    return g_blockpref[j >> 10] + g_scan_local[j];
}

// ---------------- K_setup: detect edge dtype + init + build Wc (tf32-rounded) ----------------
__global__ void k_setup(const int* __restrict__ e32,
                        const float* __restrict__ W_high,
                        const float* __restrict__ W_low) {
    int i = blockIdx.x * blockDim.x + threadIdx.x;
    if (blockIdx.x == 0) {
        int v = e32[2 * threadIdx.x + 1];       // 256 odd words sampled
        int any = __syncthreads_or(v != 0);
        if (threadIdx.x == 0) {
            g_edge_is64 = (any == 0) ? 1 : 0;
            g_scan_ticket = 0;
        }
    }
    if (i < N_NODES) { g_hist[i] = 0; g_cursor[i] = 0; }
    if (i < D_IN * D_HID) {
        int k = i / D_HID;
        int c = i % D_HID;
        float v = (c < D_OUT) ? W_high[k * D_OUT + c] : W_low[k * D_OUT + (c - D_OUT)];
        g_Wc[i] = wmma::__float_to_tf32(v);     // pre-round B once
    }
}

// ---------------- K1: TF32 WMMA GEMM (GBK=32, 2-stage) + fused epilogue ----------------
#define GBM 64
#define GBK 32
#define AS_LD 36     // 32 + 4 pad (144 B rows, 16B aligned)
#define BS_LD 132    // 128 + 4 pad (528 B rows, 16B aligned)
#define STG_LD 132   // staging: 64 x 132 floats
#define KITERS (D_IN / GBK)    // 8
#define NSTAGE 2
#define POOL_FLOATS (NSTAGE * GBM * AS_LD + NSTAGE * GBK * BS_LD)   // 13056 >= 8448
__global__ void __launch_bounds__(256, 2) k_gemm(const float* __restrict__ A,
                                                 const float* __restrict__ a_high,
                                                 const float* __restrict__ a_low) {
    __shared__ float pool[POOL_FLOATS];
    float (*As)[GBM][AS_LD] = (float(*)[GBM][AS_LD])pool;
    float (*Bs)[GBK][BS_LD] = (float(*)[GBK][BS_LD])(pool + NSTAGE * GBM * AS_LD);

    int tid = threadIdx.x;
    int wid = tid >> 5;
    int warp_row = wid & 3;
    int warp_col = wid >> 2;
    int rowBase = blockIdx.x * GBM;

    wmma::fragment<wmma::accumulator, 16, 16, 8, float> acc[4];
    #pragma unroll
    for (int q = 0; q < 4; q++) wmma::fill_fragment(acc[q], 0.0f);

    int aRow = tid >> 2;              // 0..63
    int aCol = (tid & 3) * 8;         // 0,8,16,24 (2 float4 each)
    int bRow = tid >> 3;              // 0..31
    int bCol = (tid & 7) * 16;        // 0..112 (4 float4 each)
    int gr = rowBase + aRow;
    bool aOK = gr < N_NODES;
    const float* aSrc = &A[(long)gr * D_IN + aCol];

    // stage tile 0
    {
        if (aOK) {
            cp_async16(&As[0][aRow][aCol],     aSrc);
            cp_async16(&As[0][aRow][aCol + 4], aSrc + 4);
        } else {
            *(float4*)&As[0][aRow][aCol]     = make_float4(0.f, 0.f, 0.f, 0.f);
            *(float4*)&As[0][aRow][aCol + 4] = make_float4(0.f, 0.f, 0.f, 0.f);
        }
        #pragma unroll
        for (int t = 0; t < 4; t++)
            cp_async16(&Bs[0][bRow][bCol + t * 4], &g_Wc[bRow * D_HID + bCol + t * 4]);
        asm volatile("cp.async.commit_group;");
    }

    for (int it = 0; it < KITERS; it++) {
        int buf = it & 1;
        if (it + 1 < KITERS) {
            int k0 = (it + 1) * GBK;
            int nb = buf ^ 1;
            if (aOK) {
                cp_async16(&As[nb][aRow][aCol],     aSrc + k0);
                cp_async16(&As[nb][aRow][aCol + 4], aSrc + k0 + 4);
            } else {
                *(float4*)&As[nb][aRow][aCol]     = make_float4(0.f, 0.f, 0.f, 0.f);
                *(float4*)&As[nb][aRow][aCol + 4] = make_float4(0.f, 0.f, 0.f, 0.f);
            }
            #pragma unroll
            for (int t = 0; t < 4; t++)
                cp_async16(&Bs[nb][bRow][bCol + t * 4], &g_Wc[(k0 + bRow) * D_HID + bCol + t * 4]);
            asm volatile("cp.async.commit_group;");
            asm volatile("cp.async.wait_group 1;");
        } else {
            asm volatile("cp.async.wait_group 0;");
        }
        __syncthreads();

        #pragma unroll
        for (int kk = 0; kk < GBK; kk += 8) {
            wmma::fragment<wmma::matrix_a, 16, 16, 8, wmma::precision::tf32, wmma::row_major> af;
            wmma::load_matrix_sync(af, &As[buf][warp_row * 16][kk], AS_LD);
            #pragma unroll
            for (int i = 0; i < af.num_elements; i++)
                af.x[i] = wmma::__float_to_tf32(af.x[i]);
            #pragma unroll
            for (int q = 0; q < 4; q++) {
                wmma::fragment<wmma::matrix_b, 16, 16, 8, wmma::precision::tf32, wmma::row_major> bf;
                wmma::load_matrix_sync(bf, &Bs[buf][kk][warp_col * 64 + q * 16], BS_LD);
                wmma::mma_sync(acc[q], af, bf, acc[q]);
            }
        }
        __syncthreads();
    }

    // ---- fused epilogue: leaky_relu on fragments (relu_bt min is a no-op) ----
    #pragma unroll
    for (int q = 0; q < 4; q++)
        #pragma unroll
        for (int i = 0; i < acc[q].num_elements; i++) {
            float x = acc[q].x[i];
            acc[q].x[i] = x >= 0.f ? x : BT_SLOPE * x;
        }

    // stage activated tile into reused pipeline smem
    float* stage = pool;    // 64 x STG_LD
    #pragma unroll
    for (int q = 0; q < 4; q++)
        wmma::store_matrix_sync(stage + (warp_row * 16) * STG_LD + warp_col * 64 + q * 16,
                                acc[q], STG_LD, wmma::mem_row_major);
    __syncthreads();

    // fp16 pack + s-dot. thread = (row r = tid>>2, quarter q = tid&3), 32 cols each.
    {
        int r = tid >> 2;
        int q = tid & 3;
        int gr2 = rowBase + r;
        const float* rowp = stage + r * STG_LD + q * 32;
        const float* aseg = (q < 2) ? (a_high + (q & 1) * 32) : (a_low + (q & 1) * 32);
        bool valid = gr2 < N_NODES;      // OOB rows are zeros in stage; reads are safe
        float dot = 0.f;
        #pragma unroll
        for (int b = 0; b < 4; b++) {    // 8 floats -> one uint4 (8 halves)
            float4 f0 = *(const float4*)&rowp[b * 8];
            float4 f1 = *(const float4*)&rowp[b * 8 + 4];
            __half2 h0 = __floats2half2_rn(f0.x, f0.y);
            __half2 h1 = __floats2half2_rn(f0.z, f0.w);
            __half2 h2 = __floats2half2_rn(f1.x, f1.y);
            __half2 h3 = __floats2half2_rn(f1.z, f1.w);
            uint4 u;
            u.x = *(unsigned*)&h0;
            u.y = *(unsigned*)&h1;
            u.z = *(unsigned*)&h2;
            u.w = *(unsigned*)&h3;
            if (valid) g_Hh4[(long)gr2 * 16 + q * 4 + b] = u;
            dot += f0.x * aseg[b * 8 + 0] + f0.y * aseg[b * 8 + 1]
                 + f0.z * aseg[b * 8 + 2] + f0.w * aseg[b * 8 + 3]
                 + f1.x * aseg[b * 8 + 4] + f1.y * aseg[b * 8 + 5]
                 + f1.z * aseg[b * 8 + 6] + f1.w * aseg[b * 8 + 7];
        }
        // combine quarters: q0+q1 -> s_high, q2+q3 -> s_low (shfls outside guards)
        float v = dot + __shfl_down_sync(0xffffffffu, dot, 1);
        float slow = __shfl_down_sync(0xffffffffu, v, 2);
        if (q == 0 && valid) g_s2[gr2] = make_float2(v, slow);
    }
}

// ---------------- K3: histogram of src, 4 edges/thread ----------------
__global__ void k_hist(const int* __restrict__ e32) {
    int base = (blockIdx.x * blockDim.x + threadIdx.x) * 4;
    if (base >= N_EDGES) return;                    // N_EDGES % 4 == 0
    int s[4];
    if (g_edge_is64) {
        int4 a = *(const int4*)&e32[(long)base * 2];
        int4 b = *(const int4*)&e32[(long)base * 2 + 4];
        s[0] = a.x; s[1] = a.z; s[2] = b.x; s[3] = b.z;
    } else {
        int4 a = *(const int4*)&e32[base];
        s[0] = a.x; s[1] = a.y; s[2] = a.z; s[3] = a.w;
    }
    #pragma unroll
    for (int r = 0; r < 4; r++)
        if ((unsigned)s[r] < (unsigned)N_NODES)
            atomicAdd(&g_hist[s[r]], 1);
}

// ---------------- K4: single-pass scan (fused scan1+scan2, atomic ticket) ----------------
__global__ void k_scan() {
    __shared__ int wsum[32];
    __shared__ bool isLast;
    int tid = threadIdx.x, lane = tid & 31, wid = tid >> 5;
    int i = blockIdx.x * 1024 + tid;
    int v = (i < N_NODES) ? g_hist[i] : 0;
    int inc = v;
    #pragma unroll
    for (int o = 1; o < 32; o <<= 1) {
        int tv = __shfl_up_sync(0xffffffffu, inc, o);
        if (lane >= o) inc += tv;
    }
    if (lane == 31) wsum[wid] = inc;
    __syncthreads();
    if (wid == 0) {
        int s = wsum[lane];
        #pragma unroll
        for (int o = 1; o < 32; o <<= 1) {
            int tv = __shfl_up_sync(0xffffffffu, s, o);
            if (lane >= o) s += tv;
        }
        wsum[lane] = s;
    }
    __syncthreads();
    int incl = inc + ((wid == 0) ? 0 : wsum[wid - 1]);
    if (i < N_NODES) g_scan_local[i] = incl;
    if (tid == 1023) g_blocksum[blockIdx.x] = incl;
    __threadfence();
    __syncthreads();
    if (tid == 0) {
        int t = atomicAdd(&g_scan_ticket, 1);
        isLast = (t == NB_SCAN - 1);
    }
    __syncthreads();
    if (isLast && wid == 0) {
        // final: 1 warp scans NB_SCAN block sums (2 elems/lane)
        int v0 = (2 * lane < NB_SCAN)     ? g_blocksum[2 * lane]     : 0;
        int v1 = (2 * lane + 1 < NB_SCAN) ? g_blocksum[2 * lane + 1] : 0;
        int p = v0 + v1;
        int s = p;
        #pragma unroll
        for (int o = 1; o < 32; o <<= 1) {
            int tv = __shfl_up_sync(0xffffffffu, s, o);
            if (lane >= o) s += tv;
        }
        int excl = s - p;
        if (2 * lane < NB_SCAN)     g_blockpref[2 * lane]     = excl;
        if (2 * lane + 1 < NB_SCAN) g_blockpref[2 * lane + 1] = excl + v0;
    }
}

// ---------------- K5: scatter edges into CSR by src, 2 edges/thread ----------------
__global__ void k_scatter(const int* __restrict__ e32) {
    int base = (blockIdx.x * blockDim.x + threadIdx.x) * 2;
    if (base >= N_EDGES) return;                    // N_EDGES % 2 == 0
    int s0, s1, d0, d1;
    if (g_edge_is64) {
        int4 a = *(const int4*)&e32[(long)base * 2];
        int4 b = *(const int4*)&e32[((long)N_EDGES + base) * 2];
        s0 = a.x; s1 = a.z; d0 = b.x; d1 = b.z;
    } else {
        int2 a = *(const int2*)&e32[base];
        int2 b = *(const int2*)&e32[N_EDGES + base];
        s0 = a.x; s1 = a.y; d0 = b.x; d1 = b.y;
    }
    if ((unsigned)s0 < (unsigned)N_NODES) {
        if ((unsigned)d0 >= (unsigned)N_NODES) d0 = 0;
        int pos = row_start_at(s0) + atomicAdd(&g_cursor[s0], 1);
        g_csr_dst[pos] = d0;
    }
    if ((unsigned)s1 < (unsigned)N_NODES) {
        if ((unsigned)d1 >= (unsigned)N_NODES) d1 = 0;
        int pos = row_start_at(s1) + atomicAdd(&g_cursor[s1], 1);
        g_csr_dst[pos] = d1;
    }
}

// ---------------- K6: half-warp-per-edge aggregation + fused final leaky_relu ----------------
// lane = half*16 + sub. half-warp `half` owns edge slot (j + half).
// lane covers 8 output halves: cols [sub*8, sub*8+8). sub<8 -> high half, else low.
#define PAIR_UNROLL 4
__global__ void k_agg(float* __restrict__ out) {
    int warp = (blockIdx.x * blockDim.x + threadIdx.x) >> 5;
    int lane = threadIdx.x & 31;
    if (warp >= N_NODES) return;
    int half = lane >> 4;
    int sub  = lane & 15;
    bool hiCols = sub < 8;

    int start = row_start_at(warp);
    int end   = row_start_at(warp + 1);
    float2 s_n = g_s2[warp];

    float acc[8];
    #pragma unroll
    for (int i = 0; i < 8; i++) acc[i] = 0.f;
    float wsum = 0.f;

    int j = start;
    for (; j + 2 * PAIR_UNROLL - 1 < end; j += 2 * PAIR_UNROLL) {
        int d[PAIR_UNROLL];
        float2 sd[PAIR_UNROLL];
        uint4 v[PAIR_UNROLL];
        #pragma unroll
        for (int r = 0; r < PAIR_UNROLL; r++)
            d[r] = g_csr_dst[j + 2 * r + half];      // scalar load, always aligned
        #pragma unroll
        for (int r = 0; r < PAIR_UNROLL; r++) {
            sd[r] = g_s2[d[r]];
            v[r]  = g_Hh4[(long)d[r] * 16 + sub];
        }
        #pragma unroll
        for (int r = 0; r < PAIR_UNROLL; r++) {
            float x = hiCols ? (s_n.x - sd[r].x) : (s_n.y + sd[r].y);
            float w = __expf(-(x >= 0.f ? x : ALPHA * x));
            wsum += w;
            float2 f0 = __half22float2(*(__half2*)&v[r].x);
            float2 f1 = __half22float2(*(__half2*)&v[r].y);
            float2 f2 = __half22float2(*(__half2*)&v[r].z);
            float2 f3 = __half22float2(*(__half2*)&v[r].w);
            acc[0] = fmaf(w, f0.x, acc[0]);
            acc[1] = fmaf(w, f0.y, acc[1]);
            acc[2] = fmaf(w, f1.x, acc[2]);
            acc[3] = fmaf(w, f1.y, acc[3]);
            acc[4] = fmaf(w, f2.x, acc[4]);
            acc[5] = fmaf(w, f2.y, acc[5]);
            acc[6] = fmaf(w, f3.x, acc[6]);
            acc[7] = fmaf(w, f3.y, acc[7]);
        }
    }
    for (; j + 1 < end; j += 2) {
        int d = g_csr_dst[j + half];
        float2 sd = g_s2[d];
        uint4 v = g_Hh4[(long)d * 16 + sub];
        float x = hiCols ? (s_n.x - sd.x) : (s_n.y + sd.y);
        float w = __expf(-(x >= 0.f ? x : ALPHA * x));
        wsum += w;
        float2 f0 = __half22float2(*(__half2*)&v.x);
        float2 f1 = __half22float2(*(__half2*)&v.y);
        float2 f2 = __half22float2(*(__half2*)&v.z);
        float2 f3 = __half22float2(*(__half2*)&v.w);
        acc[0] = fmaf(w, f0.x, acc[0]);
        acc[1] = fmaf(w, f0.y, acc[1]);
        acc[2] = fmaf(w, f1.x, acc[2]);
        acc[3] = fmaf(w, f1.y, acc[3]);
        acc[4] = fmaf(w, f2.x, acc[4]);
        acc[5] = fmaf(w, f2.y, acc[5]);
        acc[6] = fmaf(w, f3.x, acc[6]);
        acc[7] = fmaf(w, f3.y, acc[7]);
    }
    if (j < end) {
        int d = g_csr_dst[j];
        float2 sd = g_s2[d];
        uint4 v = g_Hh4[(long)d * 16 + sub];
        float x = hiCols ? (s_n.x - sd.x) : (s_n.y + sd.y);
        float w = __expf(-(x >= 0.f ? x : ALPHA * x));
        if (half) w = 0.f;
        wsum += w;
        float2 f0 = __half22float2(*(__half2*)&v.x);
        float2 f1 = __half22float2(*(__half2*)&v.y);
        float2 f2 = __half22float2(*(__half2*)&v.z);
        float2 f3 = __half22float2(*(__half2*)&v.w);
        acc[0] = fmaf(w, f0.x, acc[0]);
        acc[1] = fmaf(w, f0.y, acc[1]);
        acc[2] = fmaf(w, f1.x, acc[2]);
        acc[3] = fmaf(w, f1.y, acc[3]);
        acc[4] = fmaf(w, f2.x, acc[4]);
        acc[5] = fmaf(w, f2.y, acc[5]);
        acc[6] = fmaf(w, f3.x, acc[6]);
        acc[7] = fmaf(w, f3.y, acc[7]);
    }

    // combine the two edge slots (lane <-> lane^16)
    #pragma unroll
    for (int i = 0; i < 8; i++)
        acc[i] += __shfl_xor_sync(0xffffffffu, acc[i], 16);
    wsum += __shfl_xor_sync(0xffffffffu, wsum, 16);

    if (lane < 16) {
        float inv = 1.0f / (wsum + 1e-16f);
        float o[8];
        #pragma unroll
        for (int i = 0; i < 8; i++) {
            float x = acc[i] * inv;
            o[i] = x >= 0.f ? x : BT_SLOPE * x;   // final relu_bt == leaky_relu
        }
        float4 o0 = make_float4(o[0], o[1], o[2], o[3]);
        float4 o1 = make_float4(o[4], o[5], o[6], o[7]);
        *(float4*)&out[(long)warp * D_HID + sub * 8]     = o0;
        *(float4*)&out[(long)warp * D_HID + sub * 8 + 4] = o1;
    }
}

// ---------------- launch: combined setup, fork after (6 kernels total) ----------------
extern "C" void kernel_launch(void* const* d_in, const int* in_sizes, int n_in,
                              void* d_out, int out_size) {
    const float* input  = (const float*)d_in[0];
    const int*   e32    = (const int*)d_in[1];     // int32 or int64 (detected)
    const float* W_high = (const float*)d_in[2];
    const float* W_low  = (const float*)d_in[3];
    const float* a_high = (const float*)d_in[4];
    const float* a_low  = (const float*)d_in[5];
    float* out = (float*)d_out;

    cudaStream_t s2;
    cudaEvent_t evFork, evJoin;
    cudaStreamCreateWithFlags(&s2, cudaStreamNonBlocking);
    cudaEventCreateWithFlags(&evFork, cudaEventDisableTiming);
    cudaEventCreateWithFlags(&evJoin, cudaEventDisableTiming);

    k_setup<<<(N_NODES + 255) / 256, 256>>>(e32, W_high, W_low);

    // fork: edge chain on s2
    cudaEventRecord(evFork, 0);
    cudaStreamWaitEvent(s2, evFork, 0);
    k_hist<<<(N_EDGES / 4 + 255) / 256, 256, 0, s2>>>(e32);
    k_scan<<<NB_SCAN, 1024, 0, s2>>>();
    k_scatter<<<(N_EDGES / 2 + 255) / 256, 256, 0, s2>>>(e32);
    cudaEventRecord(evJoin, s2);

    // node chain on the main stream: single fused GEMM kernel
    k_gemm<<<(N_NODES + GBM - 1) / GBM, 256>>>(input, a_high, a_low);

    // join, then aggregate (final activation fused)
    cudaStreamWaitEvent(0, evJoin, 0);
    k_agg<<<(N_NODES * 32 + 255) / 256, 256>>>(out);
}

// round 16
// speedup vs baseline: 1.0206x; 1.0206x over previous
#include <cuda_runtime.h>
#include <cuda_fp16.h>
#include <mma.h>
#include <math.h>

using namespace nvcuda;

#define N_NODES 50000
#define N_EDGES 1600000
#define D_IN    256
#define D_OUT   64
#define D_HID   128   // 2*D_OUT, concat layout: [high(0..63) | low(64..127)]

#define ALPHA    0.2f
#define BT_SLOPE 0.01f

#define NB_SCAN 49    // ceil(50000/1024)

// ---------------- scratch (device globals; no cudaMalloc allowed) ----------------
__device__ float g_Wc[D_IN * D_HID];              // combined [256][128] weight, tf32-rounded
__device__ uint4 g_Hh4[N_NODES * 16];             // fp16 activated H: 128 halves/node = 16 uint4
__device__ float2 g_s2[N_NODES];                  // (s_high, s_low) per node
__device__ int g_hist[N_NODES];
__device__ int g_scan_local[N_NODES];             // inclusive scan within 1024-tile
__device__ int g_blocksum[64];
__device__ int g_blockpref[64];                   // exclusive scan of block sums
__device__ int g_rowptr[N_NODES];                 // live cursors; post-scatter: row_start(i+1)
__device__ int g_csr_dst[N_EDGES];
__device__ int g_edge_is64;

__device__ __forceinline__ void cp_async16(void* sptr, const void* gptr) {
    unsigned saddr = (unsigned)__cvta_generic_to_shared(sptr);
    asm volatile("cp.async.cg.shared.global [%0], [%1], 16;" :: "r"(saddr), "l"(gptr));
}

// ---------------- K_setup: detect edge dtype + init + build Wc (tf32-rounded) ----------------
__global__ void k_setup(const int* __restrict__ e32,
                        const float* __restrict__ W_high,
                        const float* __restrict__ W_low) {
    int i = blockIdx.x * blockDim.x + threadIdx.x;
    if (blockIdx.x == 0) {
        int v = e32[2 * threadIdx.x + 1];       // 256 odd words sampled
        int any = __syncthreads_or(v != 0);
        if (threadIdx.x == 0) g_edge_is64 = (any == 0) ? 1 : 0;
    }
    if (i < N_NODES) g_hist[i] = 0;
    if (i < D_IN * D_HID) {
        int k = i / D_HID;
        int c = i % D_HID;
        float v = (c < D_OUT) ? W_high[k * D_OUT + c] : W_low[k * D_OUT + (c - D_OUT)];
        g_Wc[i] = wmma::__float_to_tf32(v);     // pre-round B once
    }
}

// ---------------- K1: TF32 WMMA GEMM + fused leaky_relu + fp16 pack + s-dot ----------------
#define GBM 64
#define GBK 16
#define AS_LD 20
#define BS_LD 132
#define STG_LD 132   // staging: 64 x 132 floats (528B rows, 16B aligned)
#define KITERS (D_IN / GBK)
#define NSTAGE 3
#define POOL_FLOATS (NSTAGE * GBM * AS_LD + NSTAGE * GBK * BS_LD)   // 10176 >= 64*132=8448
__global__ void __launch_bounds__(256, 2) k_gemm(const float* __restrict__ A,
                                                 const float* __restrict__ a_high,
                                                 const float* __restrict__ a_low) {
    __shared__ float pool[POOL_FLOATS];
    float (*As)[GBM][AS_LD] = (float(*)[GBM][AS_LD])pool;
    float (*Bs)[GBK][BS_LD] = (float(*)[GBK][BS_LD])(pool + NSTAGE * GBM * AS_LD);

    int tid = threadIdx.x;
    int wid = tid >> 5;
    int warp_row = wid & 3;
    int warp_col = wid >> 2;
    int rowBase = blockIdx.x * GBM;

    wmma::fragment<wmma::accumulator, 16, 16, 8, float> acc[4];
    #pragma unroll
    for (int q = 0; q < 4; q++) wmma::fill_fragment(acc[q], 0.0f);

    int aRow = tid >> 2;
    int aCol = (tid & 3) * 4;
    int bRow = tid >> 4;
    int bCol = (tid & 15) * 8;
    int gr = rowBase + aRow;
    bool aOK = gr < N_NODES;
    const float* aSrc = &A[(long)gr * D_IN + aCol];

    #pragma unroll
    for (int p = 0; p < 2; p++) {
        int k0 = p * GBK;
        if (aOK) cp_async16(&As[p][aRow][aCol], aSrc + k0);
        else     *(float4*)&As[p][aRow][aCol] = make_float4(0.f, 0.f, 0.f, 0.f);
        cp_async16(&Bs[p][bRow][bCol],     &g_Wc[(k0 + bRow) * D_HID + bCol]);
        cp_async16(&Bs[p][bRow][bCol + 4], &g_Wc[(k0 + bRow) * D_HID + bCol + 4]);
        asm volatile("cp.async.commit_group;");
    }

    for (int it = 0; it < KITERS; it++) {
        int buf = it % NSTAGE;
        if (it + 2 < KITERS) {
            int k0 = (it + 2) * GBK;
            int nb = (it + 2) % NSTAGE;
            if (aOK) cp_async16(&As[nb][aRow][aCol], aSrc + k0);
            else     *(float4*)&As[nb][aRow][aCol] = make_float4(0.f, 0.f, 0.f, 0.f);
            cp_async16(&Bs[nb][bRow][bCol],     &g_Wc[(k0 + bRow) * D_HID + bCol]);
            cp_async16(&Bs[nb][bRow][bCol + 4], &g_Wc[(k0 + bRow) * D_HID + bCol + 4]);
        }
        asm volatile("cp.async.commit_group;");
        asm volatile("cp.async.wait_group 2;");
        __syncthreads();

        #pragma unroll
        for (int kk = 0; kk < GBK; kk += 8) {
            wmma::fragment<wmma::matrix_a, 16, 16, 8, wmma::precision::tf32, wmma::row_major> af;
            wmma::load_matrix_sync(af, &As[buf][warp_row * 16][kk], AS_LD);
            #pragma unroll
            for (int i = 0; i < af.num_elements; i++)
                af.x[i] = wmma::__float_to_tf32(af.x[i]);
            #pragma unroll
            for (int q = 0; q < 4; q++) {
                wmma::fragment<wmma::matrix_b, 16, 16, 8, wmma::precision::tf32, wmma::row_major> bf;
                wmma::load_matrix_sync(bf, &Bs[buf][kk][warp_col * 64 + q * 16], BS_LD);
                wmma::mma_sync(acc[q], af, bf, acc[q]);
            }
        }
        __syncthreads();
    }

    // ---- fused epilogue: leaky_relu on fragments (relu_bt min is a no-op) ----
    #pragma unroll
    for (int q = 0; q < 4; q++)
        #pragma unroll
        for (int i = 0; i < acc[q].num_elements; i++) {
            float x = acc[q].x[i];
            acc[q].x[i] = x >= 0.f ? x : BT_SLOPE * x;
        }

    // stage activated tile into reused pipeline smem
    float* stage = pool;    // 64 x STG_LD
    #pragma unroll
    for (int q = 0; q < 4; q++)
        wmma::store_matrix_sync(stage + (warp_row * 16) * STG_LD + warp_col * 64 + q * 16,
                                acc[q], STG_LD, wmma::mem_row_major);
    __syncthreads();

    // fp16 pack + s-dot. thread = (row r = tid>>2, quarter q = tid&3), 32 cols each.
    {
        int r = tid >> 2;
        int q = tid & 3;
        int gr2 = rowBase + r;
        const float* rowp = stage + r * STG_LD + q * 32;
        const float* aseg = (q < 2) ? (a_high + (q & 1) * 32) : (a_low + (q & 1) * 32);
        bool valid = gr2 < N_NODES;      // OOB rows are zeros in stage; reads are safe
        float dot = 0.f;
        #pragma unroll
        for (int b = 0; b < 4; b++) {    // 8 floats -> one uint4 (8 halves)
            float4 f0 = *(const float4*)&rowp[b * 8];
            float4 f1 = *(const float4*)&rowp[b * 8 + 4];
            __half2 h0 = __floats2half2_rn(f0.x, f0.y);
            __half2 h1 = __floats2half2_rn(f0.z, f0.w);
            __half2 h2 = __floats2half2_rn(f1.x, f1.y);
            __half2 h3 = __floats2half2_rn(f1.z, f1.w);
            uint4 u;
            u.x = *(unsigned*)&h0;
            u.y = *(unsigned*)&h1;
            u.z = *(unsigned*)&h2;
            u.w = *(unsigned*)&h3;
            if (valid) g_Hh4[(long)gr2 * 16 + q * 4 + b] = u;
            dot += f0.x * aseg[b * 8 + 0] + f0.y * aseg[b * 8 + 1]
                 + f0.z * aseg[b * 8 + 2] + f0.w * aseg[b * 8 + 3]
                 + f1.x * aseg[b * 8 + 4] + f1.y * aseg[b * 8 + 5]
                 + f1.z * aseg[b * 8 + 6] + f1.w * aseg[b * 8 + 7];
        }
        // combine quarters: q0+q1 -> s_high, q2+q3 -> s_low (shfls outside guards)
        float v = dot + __shfl_down_sync(0xffffffffu, dot, 1);
        float slow = __shfl_down_sync(0xffffffffu, v, 2);
        if (q == 0 && valid) g_s2[gr2] = make_float2(v, slow);
    }
}

// ---------------- K3: histogram of src, 4 edges/thread ----------------
__global__ void k_hist(const int* __restrict__ e32) {
    int base = (blockIdx.x * blockDim.x + threadIdx.x) * 4;
    if (base >= N_EDGES) return;                    // N_EDGES % 4 == 0
    int s[4];
    if (g_edge_is64) {
        int4 a = *(const int4*)&e32[(long)base * 2];
        int4 b = *(const int4*)&e32[(long)base * 2 + 4];
        s[0] = a.x; s[1] = a.z; s[2] = b.x; s[3] = b.z;
    } else {
        int4 a = *(const int4*)&e32[base];
        s[0] = a.x; s[1] = a.y; s[2] = a.z; s[3] = a.w;
    }
    #pragma unroll
    for (int r = 0; r < 4; r++)
        if ((unsigned)s[r] < (unsigned)N_NODES)
            atomicAdd(&g_hist[s[r]], 1);
}

// ---------------- K4a: per-1024-tile inclusive scan ----------------
__global__ void k_scan1() {
    __shared__ int wsum[32];
    int tid = threadIdx.x, lane = tid & 31, wid = tid >> 5;
    int i = blockIdx.x * 1024 + tid;
    int v = (i < N_NODES) ? g_hist[i] : 0;
    int inc = v;
    #pragma unroll
    for (int o = 1; o < 32; o <<= 1) {
        int tv = __shfl_up_sync(0xffffffffu, inc, o);
        if (lane >= o) inc += tv;
    }
    if (lane == 31) wsum[wid] = inc;
    __syncthreads();
    if (wid == 0) {
        int s = wsum[lane];
        #pragma unroll
        for (int o = 1; o < 32; o <<= 1) {
            int tv = __shfl_up_sync(0xffffffffu, s, o);
            if (lane >= o) s += tv;
        }
        wsum[lane] = s;
    }
    __syncthreads();
    int incl = inc + ((wid == 0) ? 0 : wsum[wid - 1]);
    if (i < N_NODES) g_scan_local[i] = incl;
    if (tid == 1023) g_blocksum[blockIdx.x] = incl;
}

// ---------------- K4b: scan 49 block sums (1 warp, 2 elems/lane) ----------------
__global__ void k_scan2() {
    int lane = threadIdx.x;
    int v0 = (2 * lane < NB_SCAN)     ? g_blocksum[2 * lane]     : 0;
    int v1 = (2 * lane + 1 < NB_SCAN) ? g_blocksum[2 * lane + 1] : 0;
    int p = v0 + v1;
    int inc = p;
    #pragma unroll
    for (int o = 1; o < 32; o <<= 1) {
        int tv = __shfl_up_sync(0xffffffffu, inc, o);
        if (lane >= o) inc += tv;
    }
    int excl = inc - p;
    if (2 * lane < NB_SCAN)     g_blockpref[2 * lane]     = excl;
    if (2 * lane + 1 < NB_SCAN) g_blockpref[2 * lane + 1] = excl + v0;
}

// ---------------- K4c: materialize live cursors  rowptr[i] = row_start(i) ----------------
__global__ void k_rowptr() {
    int i = blockIdx.x * blockDim.x + threadIdx.x;
    if (i >= N_NODES) return;
    int v = 0;
    if (i > 0) {
        int j = i - 1;
        v = g_blockpref[j >> 10] + g_scan_local[j];
    }
    g_rowptr[i] = v;
}

// ---------------- K5: scatter, single live-cursor atomic per edge ----------------
__global__ void k_scatter(const int* __restrict__ e32) {
    int base = (blockIdx.x * blockDim.x + threadIdx.x) * 2;
    if (base >= N_EDGES) return;                    // N_EDGES % 2 == 0
    int s0, s1, d0, d1;
    if (g_edge_is64) {
        int4 a = *(const int4*)&e32[(long)base * 2];
        int4 b = *(const int4*)&e32[((long)N_EDGES + base) * 2];
        s0 = a.x; s1 = a.z; d0 = b.x; d1 = b.z;
    } else {
        int2 a = *(const int2*)&e32[base];
        int2 b = *(const int2*)&e32[N_EDGES + base];
        s0 = a.x; s1 = a.y; d0 = b.x; d1 = b.y;
    }
    if ((unsigned)s0 < (unsigned)N_NODES) {
        if ((unsigned)d0 >= (unsigned)N_NODES) d0 = 0;
        int pos = atomicAdd(&g_rowptr[s0], 1);
        g_csr_dst[pos] = d0;
    }
    if ((unsigned)s1 < (unsigned)N_NODES) {
        if ((unsigned)d1 >= (unsigned)N_NODES) d1 = 0;
        int pos = atomicAdd(&g_rowptr[s1], 1);
        g_csr_dst[pos] = d1;
    }
}

// ---------------- K6: half-warp-per-edge aggregation + fused final leaky_relu ----------------
// post-scatter invariant: g_rowptr[i] == row_start(i+1); start = i? rowptr[i-1] : 0
#define PAIR_UNROLL 4
__global__ void k_agg(float* __restrict__ out) {
    int warp = (blockIdx.x * blockDim.x + threadIdx.x) >> 5;
    int lane = threadIdx.x & 31;
    if (warp >= N_NODES) return;
    int half = lane >> 4;
    int sub  = lane & 15;
    bool hiCols = sub < 8;

    int start = (warp == 0) ? 0 : g_rowptr[warp - 1];
    int end   = g_rowptr[warp];
    float2 s_n = g_s2[warp];

    float acc[8];
    #pragma unroll
    for (int i = 0; i < 8; i++) acc[i] = 0.f;
    float wsum = 0.f;

    int j = start;
    for (; j + 2 * PAIR_UNROLL - 1 < end; j += 2 * PAIR_UNROLL) {
        int d[PAIR_UNROLL];
        float2 sd[PAIR_UNROLL];
        uint4 v[PAIR_UNROLL];
        #pragma unroll
        for (int r = 0; r < PAIR_UNROLL; r++)
            d[r] = g_csr_dst[j + 2 * r + half];      // scalar load, always aligned
        #pragma unroll
        for (int r = 0; r < PAIR_UNROLL; r++) {
            sd[r] = g_s2[d[r]];
            v[r]  = g_Hh4[(long)d[r] * 16 + sub];
        }
        #pragma unroll
        for (int r = 0; r < PAIR_UNROLL; r++) {
            float x = hiCols ? (s_n.x - sd[r].x) : (s_n.y + sd[r].y);
            float w = __expf(-(x >= 0.f ? x : ALPHA * x));
            wsum += w;
            float2 f0 = __half22float2(*(__half2*)&v[r].x);
            float2 f1 = __half22float2(*(__half2*)&v[r].y);
            float2 f2 = __half22float2(*(__half2*)&v[r].z);
            float2 f3 = __half22float2(*(__half2*)&v[r].w);
            acc[0] = fmaf(w, f0.x, acc[0]);
            acc[1] = fmaf(w, f0.y, acc[1]);
            acc[2] = fmaf(w, f1.x, acc[2]);
            acc[3] = fmaf(w, f1.y, acc[3]);
            acc[4] = fmaf(w, f2.x, acc[4]);
            acc[5] = fmaf(w, f2.y, acc[5]);
            acc[6] = fmaf(w, f3.x, acc[6]);
            acc[7] = fmaf(w, f3.y, acc[7]);
        }
    }
    for (; j + 1 < end; j += 2) {
        int d = g_csr_dst[j + half];
        float2 sd = g_s2[d];
        uint4 v = g_Hh4[(long)d * 16 + sub];
        float x = hiCols ? (s_n.x - sd.x) : (s_n.y + sd.y);
        float w = __expf(-(x >= 0.f ? x : ALPHA * x));
        wsum += w;
        float2 f0 = __half22float2(*(__half2*)&v.x);
        float2 f1 = __half22float2(*(__half2*)&v.y);
        float2 f2 = __half22float2(*(__half2*)&v.z);
        float2 f3 = __half22float2(*(__half2*)&v.w);
        acc[0] = fmaf(w, f0.x, acc[0]);
        acc[1] = fmaf(w, f0.y, acc[1]);
        acc[2] = fmaf(w, f1.x, acc[2]);
        acc[3] = fmaf(w, f1.y, acc[3]);
        acc[4] = fmaf(w, f2.x, acc[4]);
        acc[5] = fmaf(w, f2.y, acc[5]);
        acc[6] = fmaf(w, f3.x, acc[6]);
        acc[7] = fmaf(w, f3.y, acc[7]);
    }
    if (j < end) {
        int d = g_csr_dst[j];
        float2 sd = g_s2[d];
        uint4 v = g_Hh4[(long)d * 16 + sub];
        float x = hiCols ? (s_n.x - sd.x) : (s_n.y + sd.y);
        float w = __expf(-(x >= 0.f ? x : ALPHA * x));
        if (half) w = 0.f;
        wsum += w;
        float2 f0 = __half22float2(*(__half2*)&v.x);
        float2 f1 = __half22float2(*(__half2*)&v.y);
        float2 f2 = __half22float2(*(__half2*)&v.z);
        float2 f3 = __half22float2(*(__half2*)&v.w);
        acc[0] = fmaf(w, f0.x, acc[0]);
        acc[1] = fmaf(w, f0.y, acc[1]);
        acc[2] = fmaf(w, f1.x, acc[2]);
        acc[3] = fmaf(w, f1.y, acc[3]);
        acc[4] = fmaf(w, f2.x, acc[4]);
        acc[5] = fmaf(w, f2.y, acc[5]);
        acc[6] = fmaf(w, f3.x, acc[6]);
        acc[7] = fmaf(w, f3.y, acc[7]);
    }

    // combine the two edge slots (lane <-> lane^16)
    #pragma unroll
    for (int i = 0; i < 8; i++)
        acc[i] += __shfl_xor_sync(0xffffffffu, acc[i], 16);
    wsum += __shfl_xor_sync(0xffffffffu, wsum, 16);

    if (lane < 16) {
        float inv = 1.0f / (wsum + 1e-16f);
        float o[8];
        #pragma unroll
        for (int i = 0; i < 8; i++) {
            float x = acc[i] * inv;
            o[i] = x >= 0.f ? x : BT_SLOPE * x;   // final relu_bt == leaky_relu
        }
        float4 o0 = make_float4(o[0], o[1], o[2], o[3]);
        float4 o1 = make_float4(o[4], o[5], o[6], o[7]);
        *(float4*)&out[(long)warp * D_HID + sub * 8]     = o0;
        *(float4*)&out[(long)warp * D_HID + sub * 8 + 4] = o1;
    }
}

// ---------------- launch: combined setup, fork after (R11 structure) ----------------
extern "C" void kernel_launch(void* const* d_in, const int* in_sizes, int n_in,
                              void* d_out, int out_size) {
    const float* input  = (const float*)d_in[0];
    const int*   e32    = (const int*)d_in[1];     // int32 or int64 (detected)
    const float* W_high = (const float*)d_in[2];
    const float* W_low  = (const float*)d_in[3];
    const float* a_high = (const float*)d_in[4];
    const float* a_low  = (const float*)d_in[5];
    float* out = (float*)d_out;

    cudaStream_t s2;
    cudaEvent_t evFork, evJoin;
    cudaStreamCreateWithFlags(&s2, cudaStreamNonBlocking);
    cudaEventCreateWithFlags(&evFork, cudaEventDisableTiming);
    cudaEventCreateWithFlags(&evJoin, cudaEventDisableTiming);

    k_setup<<<(N_NODES + 255) / 256, 256>>>(e32, W_high, W_low);

    // fork: edge chain on s2
    cudaEventRecord(evFork, 0);
    cudaStreamWaitEvent(s2, evFork, 0);
    k_hist<<<(N_EDGES / 4 + 255) / 256, 256, 0, s2>>>(e32);
    k_scan1<<<NB_SCAN, 1024, 0, s2>>>();
    k_scan2<<<1, 32, 0, s2>>>();
    k_rowptr<<<(N_NODES + 255) / 256, 256, 0, s2>>>();
    k_scatter<<<(N_EDGES / 2 + 255) / 256, 256, 0, s2>>>(e32);
    cudaEventRecord(evJoin, s2);

    // node chain on the main stream: single fused GEMM kernel
    k_gemm<<<(N_NODES + GBM - 1) / GBM, 256>>>(input, a_high, a_low);

    // join, then aggregate (final activation fused)
    cudaStreamWaitEvent(0, evJoin, 0);
    k_agg<<<(N_NODES * 32 + 255) / 256, 256>>>(out);
}

// round 17
// speedup vs baseline: 1.0272x; 1.0065x over previous
#include <cuda_runtime.h>
#include <cuda_fp16.h>
#include <mma.h>
#include <math.h>

using namespace nvcuda;

#define N_NODES 50000
#define N_EDGES 1600000
#define D_IN    256
#define D_OUT   64
#define D_HID   128   // 2*D_OUT, concat layout: [high(0..63) | low(64..127)]

#define ALPHA    0.2f
#define BT_SLOPE 0.01f

#define NB_SCAN 49    // ceil(50000/1024)

// ---------------- scratch (device globals; no cudaMalloc allowed) ----------------
__device__ float g_Wc[D_IN * D_HID];              // combined [256][128] weight, tf32-rounded
__device__ uint4 g_Hh4[N_NODES * 16];             // fp16 activated H: 128 halves/node = 16 uint4
__device__ float2 g_s2[N_NODES];                  // (s_high, s_low) per node
__device__ int g_hist[N_NODES];
__device__ int g_scan_local[N_NODES];             // inclusive scan within 1024-tile
__device__ int g_blocksum[64];
__device__ int g_rowptr[N_NODES];                 // live cursors; post-scatter: row_start(i+1)
__device__ int g_csr_dst[N_EDGES];
__device__ int g_edge_is64;

__device__ __forceinline__ void cp_async16(void* sptr, const void* gptr) {
    unsigned saddr = (unsigned)__cvta_generic_to_shared(sptr);
    asm volatile("cp.async.cg.shared.global [%0], [%1], 16;" :: "r"(saddr), "l"(gptr));
}

// ---------------- K_setup: detect edge dtype + init + build Wc (tf32-rounded) ----------------
__global__ void k_setup(const int* __restrict__ e32,
                        const float* __restrict__ W_high,
                        const float* __restrict__ W_low) {
    int i = blockIdx.x * blockDim.x + threadIdx.x;
    if (blockIdx.x == 0) {
        int v = e32[2 * threadIdx.x + 1];       // 256 odd words sampled
        int any = __syncthreads_or(v != 0);
        if (threadIdx.x == 0) g_edge_is64 = (any == 0) ? 1 : 0;
    }
    if (i < N_NODES) g_hist[i] = 0;
    if (i < D_IN * D_HID) {
        int k = i / D_HID;
        int c = i % D_HID;
        float v = (c < D_OUT) ? W_high[k * D_OUT + c] : W_low[k * D_OUT + (c - D_OUT)];
        g_Wc[i] = wmma::__float_to_tf32(v);     // pre-round B once
    }
}

// ---------------- K1: TF32 WMMA GEMM + fused leaky_relu + fp16 pack + s-dot ----------------
#define GBM 64
#define GBK 16
#define AS_LD 20
#define BS_LD 132
#define STG_LD 132   // staging: 64 x 132 floats (528B rows, 16B aligned)
#define KITERS (D_IN / GBK)
#define NSTAGE 3
#define POOL_FLOATS (NSTAGE * GBM * AS_LD + NSTAGE * GBK * BS_LD)   // 10176 >= 64*132=8448
__global__ void __launch_bounds__(256, 2) k_gemm(const float* __restrict__ A,
                                                 const float* __restrict__ a_high,
                                                 const float* __restrict__ a_low) {
    __shared__ float pool[POOL_FLOATS];
    float (*As)[GBM][AS_LD] = (float(*)[GBM][AS_LD])pool;
    float (*Bs)[GBK][BS_LD] = (float(*)[GBK][BS_LD])(pool + NSTAGE * GBM * AS_LD);

    int tid = threadIdx.x;
    int wid = tid >> 5;
    int warp_row = wid & 3;
    int warp_col = wid >> 2;
    int rowBase = blockIdx.x * GBM;

    wmma::fragment<wmma::accumulator, 16, 16, 8, float> acc[4];
    #pragma unroll
    for (int q = 0; q < 4; q++) wmma::fill_fragment(acc[q], 0.0f);

    int aRow = tid >> 2;
    int aCol = (tid & 3) * 4;
    int bRow = tid >> 4;
    int bCol = (tid & 15) * 8;
    int gr = rowBase + aRow;
    bool aOK = gr < N_NODES;
    const float* aSrc = &A[(long)gr * D_IN + aCol];

    #pragma unroll
    for (int p = 0; p < 2; p++) {
        int k0 = p * GBK;
        if (aOK) cp_async16(&As[p][aRow][aCol], aSrc + k0);
        else     *(float4*)&As[p][aRow][aCol] = make_float4(0.f, 0.f, 0.f, 0.f);
        cp_async16(&Bs[p][bRow][bCol],     &g_Wc[(k0 + bRow) * D_HID + bCol]);
        cp_async16(&Bs[p][bRow][bCol + 4], &g_Wc[(k0 + bRow) * D_HID + bCol + 4]);
        asm volatile("cp.async.commit_group;");
    }

    for (int it = 0; it < KITERS; it++) {
        int buf = it % NSTAGE;
        if (it + 2 < KITERS) {
            int k0 = (it + 2) * GBK;
            int nb = (it + 2) % NSTAGE;
            if (aOK) cp_async16(&As[nb][aRow][aCol], aSrc + k0);
            else     *(float4*)&As[nb][aRow][aCol] = make_float4(0.f, 0.f, 0.f, 0.f);
            cp_async16(&Bs[nb][bRow][bCol],     &g_Wc[(k0 + bRow) * D_HID + bCol]);
            cp_async16(&Bs[nb][bRow][bCol + 4], &g_Wc[(k0 + bRow) * D_HID + bCol + 4]);
        }
        asm volatile("cp.async.commit_group;");
        asm volatile("cp.async.wait_group 2;");
        __syncthreads();

        #pragma unroll
        for (int kk = 0; kk < GBK; kk += 8) {
            wmma::fragment<wmma::matrix_a, 16, 16, 8, wmma::precision::tf32, wmma::row_major> af;
            wmma::load_matrix_sync(af, &As[buf][warp_row * 16][kk], AS_LD);
            #pragma unroll
            for (int i = 0; i < af.num_elements; i++)
                af.x[i] = wmma::__float_to_tf32(af.x[i]);
            #pragma unroll
            for (int q = 0; q < 4; q++) {
                wmma::fragment<wmma::matrix_b, 16, 16, 8, wmma::precision::tf32, wmma::row_major> bf;
                wmma::load_matrix_sync(bf, &Bs[buf][kk][warp_col * 64 + q * 16], BS_LD);
                wmma::mma_sync(acc[q], af, bf, acc[q]);
            }
        }
        __syncthreads();
    }

    // ---- fused epilogue: leaky_relu on fragments (relu_bt min is a no-op) ----
    #pragma unroll
    for (int q = 0; q < 4; q++)
        #pragma unroll
        for (int i = 0; i < acc[q].num_elements; i++) {
            float x = acc[q].x[i];
            acc[q].x[i] = x >= 0.f ? x : BT_SLOPE * x;
        }

    // stage activated tile into reused pipeline smem
    float* stage = pool;    // 64 x STG_LD
    #pragma unroll
    for (int q = 0; q < 4; q++)
        wmma::store_matrix_sync(stage + (warp_row * 16) * STG_LD + warp_col * 64 + q * 16,
                                acc[q], STG_LD, wmma::mem_row_major);
    __syncthreads();

    // fp16 pack + s-dot. thread = (row r = tid>>2, quarter q = tid&3), 32 cols each.
    {
        int r = tid >> 2;
        int q = tid & 3;
        int gr2 = rowBase + r;
        const float* rowp = stage + r * STG_LD + q * 32;
        const float* aseg = (q < 2) ? (a_high + (q & 1) * 32) : (a_low + (q & 1) * 32);
        bool valid = gr2 < N_NODES;      // OOB rows are zeros in stage; reads are safe
        float dot = 0.f;
        #pragma unroll
        for (int b = 0; b < 4; b++) {    // 8 floats -> one uint4 (8 halves)
            float4 f0 = *(const float4*)&rowp[b * 8];
            float4 f1 = *(const float4*)&rowp[b * 8 + 4];
            __half2 h0 = __floats2half2_rn(f0.x, f0.y);
            __half2 h1 = __floats2half2_rn(f0.z, f0.w);
            __half2 h2 = __floats2half2_rn(f1.x, f1.y);
            __half2 h3 = __floats2half2_rn(f1.z, f1.w);
            uint4 u;
            u.x = *(unsigned*)&h0;
            u.y = *(unsigned*)&h1;
            u.z = *(unsigned*)&h2;
            u.w = *(unsigned*)&h3;
            if (valid) g_Hh4[(long)gr2 * 16 + q * 4 + b] = u;
            dot += f0.x * aseg[b * 8 + 0] + f0.y * aseg[b * 8 + 1]
                 + f0.z * aseg[b * 8 + 2] + f0.w * aseg[b * 8 + 3]
                 + f1.x * aseg[b * 8 + 4] + f1.y * aseg[b * 8 + 5]
                 + f1.z * aseg[b * 8 + 6] + f1.w * aseg[b * 8 + 7];
        }
        // combine quarters: q0+q1 -> s_high, q2+q3 -> s_low (shfls outside guards)
        float v = dot + __shfl_down_sync(0xffffffffu, dot, 1);
        float slow = __shfl_down_sync(0xffffffffu, v, 2);
        if (q == 0 && valid) g_s2[gr2] = make_float2(v, slow);
    }
}

// ---------------- K3: histogram of src, 4 edges/thread ----------------
__global__ void k_hist(const int* __restrict__ e32) {
    int base = (blockIdx.x * blockDim.x + threadIdx.x) * 4;
    if (base >= N_EDGES) return;                    // N_EDGES % 4 == 0
    int s[4];
    if (g_edge_is64) {
        int4 a = *(const int4*)&e32[(long)base * 2];
        int4 b = *(const int4*)&e32[(long)base * 2 + 4];
        s[0] = a.x; s[1] = a.z; s[2] = b.x; s[3] = b.z;
    } else {
        int4 a = *(const int4*)&e32[base];
        s[0] = a.x; s[1] = a.y; s[2] = a.z; s[3] = a.w;
    }
    #pragma unroll
    for (int r = 0; r < 4; r++)
        if ((unsigned)s[r] < (unsigned)N_NODES)
            atomicAdd(&g_hist[s[r]], 1);
}

// ---------------- K4a: per-1024-tile inclusive scan ----------------
__global__ void k_scan1() {
    __shared__ int wsum[32];
    int tid = threadIdx.x, lane = tid & 31, wid = tid >> 5;
    int i = blockIdx.x * 1024 + tid;
    int v = (i < N_NODES) ? g_hist[i] : 0;
    int inc = v;
    #pragma unroll
    for (int o = 1; o < 32; o <<= 1) {
        int tv = __shfl_up_sync(0xffffffffu, inc, o);
        if (lane >= o) inc += tv;
    }
    if (lane == 31) wsum[wid] = inc;
    __syncthreads();
    if (wid == 0) {
        int s = wsum[lane];
        #pragma unroll
        for (int o = 1; o < 32; o <<= 1) {
            int tv = __shfl_up_sync(0xffffffffu, s, o);
            if (lane >= o) s += tv;
        }
        wsum[lane] = s;
    }
    __syncthreads();
    int incl = inc + ((wid == 0) ? 0 : wsum[wid - 1]);
    if (i < N_NODES) g_scan_local[i] = incl;
    if (tid == 1023) g_blocksum[blockIdx.x] = incl;
}

// ---------------- K4b: fused blocksum-scan + rowptr materialization ----------------
// Each of the 49 blocks redundantly scans the 49 block sums (1 warp, smem),
// then writes its 1024 rowptr entries. Removes the separate scan2/rowptr launches.
__global__ void k_scan2rp() {
    __shared__ int pref[64];
    int tid = threadIdx.x;
    if (tid < 32) {
        int lane = tid;
        int v0 = (2 * lane < NB_SCAN)     ? g_blocksum[2 * lane]     : 0;
        int v1 = (2 * lane + 1 < NB_SCAN) ? g_blocksum[2 * lane + 1] : 0;
        int p = v0 + v1;
        int inc = p;
        #pragma unroll
        for (int o = 1; o < 32; o <<= 1) {
            int tv = __shfl_up_sync(0xffffffffu, inc, o);
            if (lane >= o) inc += tv;
        }
        int excl = inc - p;
        if (2 * lane < NB_SCAN)     pref[2 * lane]     = excl;
        if (2 * lane + 1 < NB_SCAN) pref[2 * lane + 1] = excl + v0;
    }
    __syncthreads();
    int i = blockIdx.x * 1024 + tid;
    if (i >= N_NODES) return;
    int v = 0;
    if (i > 0) {
        int j = i - 1;
        v = pref[j >> 10] + g_scan_local[j];
    }
    g_rowptr[i] = v;
}

// ---------------- K5: scatter, single live-cursor atomic per edge ----------------
__global__ void k_scatter(const int* __restrict__ e32) {
    int base = (blockIdx.x * blockDim.x + threadIdx.x) * 2;
    if (base >= N_EDGES) return;                    // N_EDGES % 2 == 0
    int s0, s1, d0, d1;
    if (g_edge_is64) {
        int4 a = *(const int4*)&e32[(long)base * 2];
        int4 b = *(const int4*)&e32[((long)N_EDGES + base) * 2];
        s0 = a.x; s1 = a.z; d0 = b.x; d1 = b.z;
    } else {
        int2 a = *(const int2*)&e32[base];
        int2 b = *(const int2*)&e32[N_EDGES + base];
        s0 = a.x; s1 = a.y; d0 = b.x; d1 = b.y;
    }
    if ((unsigned)s0 < (unsigned)N_NODES) {
        if ((unsigned)d0 >= (unsigned)N_NODES) d0 = 0;
        int pos = atomicAdd(&g_rowptr[s0], 1);
        g_csr_dst[pos] = d0;
    }
    if ((unsigned)s1 < (unsigned)N_NODES) {
        if ((unsigned)d1 >= (unsigned)N_NODES) d1 = 0;
        int pos = atomicAdd(&g_rowptr[s1], 1);
        g_csr_dst[pos] = d1;
    }
}

// ---------------- K6: half-warp-per-edge aggregation + fused final leaky_relu ----------------
// post-scatter invariant: g_rowptr[i] == row_start(i+1); start = i? rowptr[i-1] : 0
#define PAIR_UNROLL 4
__global__ void k_agg(float* __restrict__ out) {
    int warp = (blockIdx.x * blockDim.x + threadIdx.x) >> 5;
    int lane = threadIdx.x & 31;
    if (warp >= N_NODES) return;
    int half = lane >> 4;
    int sub  = lane & 15;
    bool hiCols = sub < 8;

    int start = (warp == 0) ? 0 : g_rowptr[warp - 1];
    int end   = g_rowptr[warp];
    float2 s_n = g_s2[warp];

    float acc[8];
    #pragma unroll
    for (int i = 0; i < 8; i++) acc[i] = 0.f;
    float wsum = 0.f;

    int j = start;
    for (; j + 2 * PAIR_UNROLL - 1 < end; j += 2 * PAIR_UNROLL) {
        int d[PAIR_UNROLL];
        float2 sd[PAIR_UNROLL];
        uint4 v[PAIR_UNROLL];
        #pragma unroll
        for (int r = 0; r < PAIR_UNROLL; r++)
            d[r] = g_csr_dst[j + 2 * r + half];      // scalar load, always aligned
        #pragma unroll
        for (int r = 0; r < PAIR_UNROLL; r++) {
            sd[r] = g_s2[d[r]];
            v[r]  = g_Hh4[(long)d[r] * 16 + sub];
        }
        #pragma unroll
        for (int r = 0; r < PAIR_UNROLL; r++) {
            float x = hiCols ? (s_n.x - sd[r].x) : (s_n.y + sd[r].y);
            float w = __expf(-(x >= 0.f ? x : ALPHA * x));
            wsum += w;
            float2 f0 = __half22float2(*(__half2*)&v[r].x);
            float2 f1 = __half22float2(*(__half2*)&v[r].y);
            float2 f2 = __half22float2(*(__half2*)&v[r].z);
            float2 f3 = __half22float2(*(__half2*)&v[r].w);
            acc[0] = fmaf(w, f0.x, acc[0]);
            acc[1] = fmaf(w, f0.y, acc[1]);
            acc[2] = fmaf(w, f1.x, acc[2]);
            acc[3] = fmaf(w, f1.y, acc[3]);
            acc[4] = fmaf(w, f2.x, acc[4]);
            acc[5] = fmaf(w, f2.y, acc[5]);
            acc[6] = fmaf(w, f3.x, acc[6]);
            acc[7] = fmaf(w, f3.y, acc[7]);
        }
    }
    for (; j + 1 < end; j += 2) {
        int d = g_csr_dst[j + half];
        float2 sd = g_s2[d];
        uint4 v = g_Hh4[(long)d * 16 + sub];
        float x = hiCols ? (s_n.x - sd.x) : (s_n.y + sd.y);
        float w = __expf(-(x >= 0.f ? x : ALPHA * x));
        wsum += w;
        float2 f0 = __half22float2(*(__half2*)&v.x);
        float2 f1 = __half22float2(*(__half2*)&v.y);
        float2 f2 = __half22float2(*(__half2*)&v.z);
        float2 f3 = __half22float2(*(__half2*)&v.w);
        acc[0] = fmaf(w, f0.x, acc[0]);
        acc[1] = fmaf(w, f0.y, acc[1]);
        acc[2] = fmaf(w, f1.x, acc[2]);
        acc[3] = fmaf(w, f1.y, acc[3]);
        acc[4] = fmaf(w, f2.x, acc[4]);
        acc[5] = fmaf(w, f2.y, acc[5]);
        acc[6] = fmaf(w, f3.x, acc[6]);
        acc[7] = fmaf(w, f3.y, acc[7]);
    }
    if (j < end) {
        int d = g_csr_dst[j];
        float2 sd = g_s2[d];
        uint4 v = g_Hh4[(long)d * 16 + sub];
        float x = hiCols ? (s_n.x - sd.x) : (s_n.y + sd.y);
        float w = __expf(-(x >= 0.f ? x : ALPHA * x));
        if (half) w = 0.f;
        wsum += w;
        float2 f0 = __half22float2(*(__half2*)&v.x);
        float2 f1 = __half22float2(*(__half2*)&v.y);
        float2 f2 = __half22float2(*(__half2*)&v.z);
        float2 f3 = __half22float2(*(__half2*)&v.w);
        acc[0] = fmaf(w, f0.x, acc[0]);
        acc[1] = fmaf(w, f0.y, acc[1]);
        acc[2] = fmaf(w, f1.x, acc[2]);
        acc[3] = fmaf(w, f1.y, acc[3]);
        acc[4] = fmaf(w, f2.x, acc[4]);
        acc[5] = fmaf(w, f2.y, acc[5]);
        acc[6] = fmaf(w, f3.x, acc[6]);
        acc[7] = fmaf(w, f3.y, acc[7]);
    }

    // combine the two edge slots (lane <-> lane^16)
    #pragma unroll
    for (int i = 0; i < 8; i++)
        acc[i] += __shfl_xor_sync(0xffffffffu, acc[i], 16);
    wsum += __shfl_xor_sync(0xffffffffu, wsum, 16);

    if (lane < 16) {
        float inv = 1.0f / (wsum + 1e-16f);
        float o[8];
        #pragma unroll
        for (int i = 0; i < 8; i++) {
            float x = acc[i] * inv;
            o[i] = x >= 0.f ? x : BT_SLOPE * x;   // final relu_bt == leaky_relu
        }
        float4 o0 = make_float4(o[0], o[1], o[2], o[3]);
        float4 o1 = make_float4(o[4], o[5], o[6], o[7]);
        *(float4*)&out[(long)warp * D_HID + sub * 8]     = o0;
        *(float4*)&out[(long)warp * D_HID + sub * 8 + 4] = o1;
    }
}

// ---------------- launch: gemm submitted 4th so ncu (-s 5 -c 1) captures it ----------------
extern "C" void kernel_launch(void* const* d_in, const int* in_sizes, int n_in,
                              void* d_out, int out_size) {
    const float* input  = (const float*)d_in[0];
    const int*   e32    = (const int*)d_in[1];     // int32 or int64 (detected)
    const float* W_high = (const float*)d_in[2];
    const float* W_low  = (const float*)d_in[3];
    const float* a_high = (const float*)d_in[4];
    const float* a_low  = (const float*)d_in[5];
    float* out = (float*)d_out;

    cudaStream_t s2;
    cudaEvent_t evFork, evJoin;
    cudaStreamCreateWithFlags(&s2, cudaStreamNonBlocking);
    cudaEventCreateWithFlags(&evFork, cudaEventDisableTiming);
    cudaEventCreateWithFlags(&evJoin, cudaEventDisableTiming);

    k_setup<<<(N_NODES + 255) / 256, 256>>>(e32, W_high, W_low);           // launch 1

    cudaEventRecord(evFork, 0);
    cudaStreamWaitEvent(s2, evFork, 0);

    k_hist<<<(N_EDGES / 4 + 255) / 256, 256, 0, s2>>>(e32);                 // launch 2
    k_scan1<<<NB_SCAN, 1024, 0, s2>>>();                                    // launch 3
    k_gemm<<<(N_NODES + GBM - 1) / GBM, 256>>>(input, a_high, a_low);       // launch 4 (profiled)
    k_scan2rp<<<NB_SCAN, 1024, 0, s2>>>();                                  // launch 5
    k_scatter<<<(N_EDGES / 2 + 255) / 256, 256, 0, s2>>>(e32);              // launch 6
    cudaEventRecord(evJoin, s2);

    cudaStreamWaitEvent(0, evJoin, 0);
    k_agg<<<(N_NODES * 32 + 255) / 256, 256>>>(out);                        // launch 7
}